// round 15
// baseline (speedup 1.0000x reference)
#include <cuda_runtime.h>
#include <math.h>

#define NN 100000
#define EE 800000
#define DOUT 47
#define BCAP 32
#define GT 1563             // 64-row GEMM tiles
#define GB 391              // GEMM blocks; block b does tiles b+t*391, t<4

// Scratch (allocation-free rule: static device globals).
// g_h / g_h2 have one extra row (index NN): all-zero gather target for padding.
__device__ float g_h [(size_t)(NN + 1) * 64];
__device__ float g_h2[(size_t)(NN + 1) * 64];
__device__ float g_agg[(size_t)NN * 64];
__device__ int   g_deg[NN];          // after pad_kernel: >=8, multiple of 8
__device__ int   g_bkt[(size_t)NN * BCAP];
__device__ int   g_idx64;

// ---------------------------------------------------------------------------
// Packed fp32x2 FMA (Blackwell FFMA2 — only reachable via PTX)
// ---------------------------------------------------------------------------
__device__ __forceinline__ void ffma2(unsigned long long& acc,
                                      unsigned long long a,
                                      unsigned long long b) {
    asm("fma.rn.f32x2 %0, %1, %2, %0;" : "+l"(acc) : "l"(a), "l"(b));
}
__device__ __forceinline__ float acc_sum(unsigned long long acc) {
    float lo = __uint_as_float((unsigned)(acc & 0xffffffffu));
    float hi = __uint_as_float((unsigned)(acc >> 32));
    return lo + hi;
}

// ---------------------------------------------------------------------------
// zero degree array + detect edge dtype + zero the 64-wide padding rows
// ---------------------------------------------------------------------------
__global__ void zero_detect_kernel(const void* ei) {
    int i = blockIdx.x * blockDim.x + threadIdx.x;
    if (i < NN) g_deg[i] = 0;
    if (blockIdx.x == 0) {
        __shared__ int bad;
        if (threadIdx.x == 0) bad = 0;
        __syncthreads();
        const long long* p = (const long long*)ei;
        for (int j = threadIdx.x; j < 4096; j += blockDim.x) {
            long long v = p[j];
            if (v < 0 || v >= NN) bad = 1;
        }
        __syncthreads();
        if (threadIdx.x == 0) g_idx64 = bad ? 0 : 1;
    }
    if (blockIdx.x == 1 && threadIdx.x < 64) {
        g_h [(size_t)NN * 64 + threadIdx.x] = 0.f;
        g_h2[(size_t)NN * 64 + threadIdx.x] = 0.f;
    }
}

// ---------------------------------------------------------------------------
// Bucket fill: bkt[dst][pos++] = src
// ---------------------------------------------------------------------------
__global__ void bucket_fill_kernel(const void* ei) {
    int e = blockIdx.x * blockDim.x + threadIdx.x;
    if (e >= EE) return;
    int src, dst;
    if (g_idx64) {
        const long long* p = (const long long*)ei;
        src = (int)p[e];
        dst = (int)p[EE + e];
    } else {
        const int* p = (const int*)ei;
        src = p[e];
        dst = p[EE + e];
    }
    int pos = atomicAdd(&g_deg[dst], 1);
    if (pos < BCAP) g_bkt[(size_t)dst * BCAP + pos] = src;
}

// ---------------------------------------------------------------------------
// Pad each bucket to >=8, multiple of 8, with sentinel NN (zero row).
// ---------------------------------------------------------------------------
__global__ void pad_kernel() {
    int i = blockIdx.x * blockDim.x + threadIdx.x;
    if (i >= NN) return;
    int d  = min(g_deg[i], BCAP);
    int d8 = (d + 7) & ~7;
    if (d8 < 8) d8 = 8;
    int* bp = &g_bkt[(size_t)i * BCAP];
    for (int j = d; j < d8; j++) bp[j] = NN;
    g_deg[i] = d8;
}

// ---------------------------------------------------------------------------
// GEMM: out[*, 0..DP) = in[*, 0..63] @ W[64, wcols] (zero-padded to DP).
// k-pair FFMA2 scheme: acc f32x2 holds even-k in lo, odd-k in hi; one
// LDS.128 of xs gives 4 k-values, one LDS.128 of W^T gives 4 k-values of a
// column. No pack MOVs. 64-row tiles, 391 blocks x 4 tiles (balanced,
// 4 blocks/SM, 34.8KB static smem, <=64 regs). Thread (rg=tid>>3, cg=tid&7):
// rows rg, rg+32; cols cg+8j (j<NJ). W^T stride 68 -> conflict-free quads.
// ZP (DP=48 only): zero the 48-wide pad row (runs after gemm1 reused the
// buffer 64-wide, before the LSM gather reads it).
// ---------------------------------------------------------------------------
template <int DP, bool ZP>   // DP = 64 or 48
__global__ void __launch_bounds__(256, 4)
gemm_kernel(const float* __restrict__ in, const float* __restrict__ W,
            int wcols, float* __restrict__ out) {
    constexpr int NJ = DP / 8;         // cols per thread (8 or 6)
    __shared__ float xs[64 * 68];
    __shared__ float wst[DP * 68];     // W transposed: wst[c*68 + k]

    const int tid = threadIdx.x;
    if (ZP && blockIdx.x == 0 && tid < 64)
        out[(size_t)NN * 48 + tid] = 0.f;   // covers CH=12 sentinel reads

    // Stage W^T (coalesced read, transposed write)
    for (int i = tid; i < 64 * DP; i += 256) {
        int c = i % DP, k = i / DP;
        wst[c * 68 + k] = (c < wcols) ? W[k * wcols + c] : 0.f;
    }

    const int rg = tid >> 3;    // 0..31: rows rg, rg+32
    const int cg = tid & 7;

#pragma unroll 1
    for (int t = 0; t < 4; t++) {
        const int tile = blockIdx.x + t * GB;
        if (tile >= GT) break;
        const int row0 = tile * 64;

        if (t) __syncthreads();
        for (int i = tid; i < 64 * 16; i += 256) {
            int r = i >> 4, c4 = i & 15;
            int gr = row0 + r;
            float4 v = (gr < NN) ? ((const float4*)in)[(size_t)gr * 16 + c4]
                                 : make_float4(0.f, 0.f, 0.f, 0.f);
            *(float4*)&xs[r * 68 + c4 * 4] = v;
        }
        __syncthreads();

        unsigned long long acc0[NJ], acc1[NJ];
#pragma unroll
        for (int j = 0; j < NJ; j++) { acc0[j] = 0ULL; acc1[j] = 0ULL; }

        const float* xr0 = &xs[rg * 68];
        const float* xr1 = &xs[(rg + 32) * 68];

#pragma unroll
        for (int k4 = 0; k4 < 16; k4++) {
            ulonglong2 xa = *(const ulonglong2*)&xr0[k4 * 4];  // {k0k1,k2k3}
            ulonglong2 xb = *(const ulonglong2*)&xr1[k4 * 4];
#pragma unroll
            for (int j = 0; j < NJ; j++) {
                ulonglong2 w =
                    *(const ulonglong2*)&wst[(cg + 8 * j) * 68 + k4 * 4];
                ffma2(acc0[j], xa.x, w.x);
                ffma2(acc1[j], xb.x, w.x);
                ffma2(acc0[j], xa.y, w.y);
                ffma2(acc1[j], xb.y, w.y);
            }
        }

        int r0 = row0 + rg, r1 = r0 + 32;
        if (r0 < NN) {
#pragma unroll
            for (int j = 0; j < NJ; j++)
                out[(size_t)r0 * DP + cg + 8 * j] = acc_sum(acc0[j]);
        }
        if (r1 < NN) {
#pragma unroll
            for (int j = 0; j < NJ; j++)
                out[(size_t)r1 * DP + cg + 8 * j] = acc_sum(acc1[j]);
        }
    }
}

// ---------------------------------------------------------------------------
// Gather: out[n] = epi(bias + sum_{e in bkt[n]} h[src[e]]). 16 lanes/node.
// deg padded to >=8 multiple of 8: first 8-batch unconditional (do-while).
// ---------------------------------------------------------------------------
template <int CH, bool LSM>
__global__ void gather_kernel(const float* __restrict__ h,
                              const float* __restrict__ bias, int bcols,
                              float* __restrict__ outp) {
    int t = blockIdx.x * blockDim.x + threadIdx.x;
    int n = t >> 4;
    if (n >= NN) return;
    int ln = t & 15;

    const bool act = (ln < CH);
    float4 a = make_float4(0.f, 0.f, 0.f, 0.f);
    float4 b = a;
    if (act) {
        int c = ln * 4;
        a.x = bias[c];
        a.y = bias[c + 1];
        a.z = bias[c + 2];
        a.w = (c + 3 < bcols) ? bias[c + 3] : 0.f;
    }

    const int deg8 = g_deg[n];               // >= 8, multiple of 8
    const int* bp = &g_bkt[(size_t)n * BCAP];
    const float4* h4 = (const float4*)h;

    int e = 0;
    do {
        int4 i0 = *(const int4*)(bp + e);
        int4 i1 = *(const int4*)(bp + e + 4);
        if (act) {
            float4 v0 = h4[(size_t)i0.x * CH + ln];
            float4 v1 = h4[(size_t)i0.y * CH + ln];
            float4 v2 = h4[(size_t)i0.z * CH + ln];
            float4 v3 = h4[(size_t)i0.w * CH + ln];
            float4 v4 = h4[(size_t)i1.x * CH + ln];
            float4 v5 = h4[(size_t)i1.y * CH + ln];
            float4 v6 = h4[(size_t)i1.z * CH + ln];
            float4 v7 = h4[(size_t)i1.w * CH + ln];
            a.x += (v0.x + v1.x) + (v2.x + v3.x);
            a.y += (v0.y + v1.y) + (v2.y + v3.y);
            a.z += (v0.z + v1.z) + (v2.z + v3.z);
            a.w += (v0.w + v1.w) + (v2.w + v3.w);
            b.x += (v4.x + v5.x) + (v6.x + v7.x);
            b.y += (v4.y + v5.y) + (v6.y + v7.y);
            b.z += (v4.z + v5.z) + (v6.z + v7.z);
            b.w += (v4.w + v5.w) + (v6.w + v7.w);
        }
        e += 8;
    } while (e < deg8);
    a.x += b.x; a.y += b.y; a.z += b.z; a.w += b.w;

    if (!LSM) {
        a.x = fmaxf(a.x, 0.f); a.y = fmaxf(a.y, 0.f);
        a.z = fmaxf(a.z, 0.f); a.w = fmaxf(a.w, 0.f);
        if (act) ((float4*)outp)[(size_t)n * CH + ln] = a;
    } else {
        float e0 = a.x, e1 = a.y, e2 = a.z, e3 = a.w;
        bool v3ok = (ln * 4 + 3 < DOUT);
        if (!act)       { e0 = e1 = e2 = e3 = -INFINITY; }
        else if (!v3ok) { e3 = -INFINITY; }

        float m = fmaxf(fmaxf(e0, e1), fmaxf(e2, e3));
#pragma unroll
        for (int off = 8; off; off >>= 1)
            m = fmaxf(m, __shfl_xor_sync(0xFFFFFFFFu, m, off));

        float s = 0.f;
        if (act) {
            s = expf(e0 - m) + expf(e1 - m) + expf(e2 - m);
            if (v3ok) s += expf(e3 - m);
        }
#pragma unroll
        for (int off = 8; off; off >>= 1)
            s += __shfl_xor_sync(0xFFFFFFFFu, s, off);

        float lse = m + logf(s);
        if (act) {
            size_t o = (size_t)n * DOUT + ln * 4;
            outp[o]     = e0 - lse;
            outp[o + 1] = e1 - lse;
            outp[o + 2] = e2 - lse;
            if (v3ok) outp[o + 3] = e3 - lse;
        }
    }
}

// ---------------------------------------------------------------------------
extern "C" void kernel_launch(void* const* d_in, const int* in_sizes, int n_in,
                              void* d_out, int out_size) {
    const float* x  = (const float*)d_in[0];
    const void*  ei = d_in[1];
    const float* W1 = (const float*)d_in[2];
    const float* b1 = (const float*)d_in[3];
    const float* W2 = (const float*)d_in[4];
    const float* b2 = (const float*)d_in[5];
    const float* W3 = (const float*)d_in[6];
    const float* b3 = (const float*)d_in[7];
    float* out = (float*)d_out;

    float *h_ptr, *h2_ptr, *agg_ptr;
    cudaGetSymbolAddress((void**)&h_ptr,  g_h);
    cudaGetSymbolAddress((void**)&h2_ptr, g_h2);
    cudaGetSymbolAddress((void**)&agg_ptr, g_agg);

    static cudaStream_t s2 = nullptr;
    static cudaEvent_t evFork, evJoin;
    if (!s2) {
        cudaStreamCreateWithFlags(&s2, cudaStreamNonBlocking);
        cudaEventCreateWithFlags(&evFork, cudaEventDisableTiming);
        cudaEventCreateWithFlags(&evJoin, cudaEventDisableTiming);
    }

    const int EDGE_BLKS = (EE + 255) / 256;                    // 3125
    const int NODE_BLKS = (NN + 255) / 256;                    // 391
    const int GATH_BLKS = ((long long)NN * 16 + 255) / 256;    // 6250

    // --- Fork: bucket build + padding on s2, concurrent with layer-1 GEMM ---
    cudaEventRecord(evFork, 0);
    cudaStreamWaitEvent(s2, evFork, 0);
    zero_detect_kernel<<<NODE_BLKS, 256, 0, s2>>>(ei);           // launch 1
    bucket_fill_kernel<<<EDGE_BLKS, 256, 0, s2>>>(ei);           // launch 2
    pad_kernel<<<NODE_BLKS, 256, 0, s2>>>();                     // launch 3
    cudaEventRecord(evJoin, s2);

    // Layer-1 GEMM on main stream: g_h = x @ W1
    gemm_kernel<64, false><<<GB, 256>>>(x, W1, 64, h_ptr);       // launch 4
    cudaStreamWaitEvent(0, evJoin, 0);

    // Layer 1 aggregate
    gather_kernel<16, false><<<GATH_BLKS, 256>>>(h_ptr, b1, 64, agg_ptr); // 5

    // Layer 2 (launch 6 — ncu capture target: gemm2)
    gemm_kernel<64, false><<<GB, 256>>>(agg_ptr, W2, 64, h2_ptr);
    gather_kernel<16, false><<<GATH_BLKS, 256>>>(h2_ptr, b2, 64, agg_ptr);

    // Layer 3 (48-wide, zeroes its own pad row) + fused log_softmax
    gemm_kernel<48, true><<<GB, 256>>>(agg_ptr, W3, 47, h_ptr);
    gather_kernel<12, true><<<GATH_BLKS, 256>>>(h_ptr, b3, 47, out);
}

// round 17
// speedup vs baseline: 1.4416x; 1.4416x over previous
#include <cuda_runtime.h>
#include <cuda_bf16.h>
#include <math.h>
#include <stdint.h>

#define NN 100000
#define EE 800000
#define DOUT 47
#define BCAP 64
#define GTILES 782          // 128-row GEMM tiles

// SMEM byte offsets for the HMMA GEMM (row stride 144B = 72 bf16)
#define AHI_OFF 0           // 128 x 144B = 18432
#define ALO_OFF 18432
#define BHI_OFF 36864       // 64 x 144B = 9216
#define BLO_OFF 46080
#define SM_TOT  55296

// Scratch (allocation-free rule: static device globals).
// g_h / g_h2 have one extra row (index NN): all-zero gather target for padding.
__device__ float g_h [(size_t)(NN + 1) * 64];
__device__ float g_h2[(size_t)(NN + 1) * 64];
__device__ float g_agg[(size_t)NN * 64];
__device__ int   g_deg[NN];          // after pad_kernel: >=8, multiple of 8
__device__ int   g_bkt[(size_t)NN * BCAP];
__device__ int   g_idx64;

// ---------------------------------------------------------------------------
// HMMA m16n8k16 bf16 (row.col, fp32 accum) — plain sm_80+ PTX, no 'a' feature
// ---------------------------------------------------------------------------
__device__ __forceinline__ void mma16816(float* d, const uint32_t* a,
                                         uint32_t b0, uint32_t b1) {
    asm volatile(
        "mma.sync.aligned.m16n8k16.row.col.f32.bf16.bf16.f32 "
        "{%0,%1,%2,%3}, {%4,%5,%6,%7}, {%8,%9}, {%0,%1,%2,%3};"
        : "+f"(d[0]), "+f"(d[1]), "+f"(d[2]), "+f"(d[3])
        : "r"(a[0]), "r"(a[1]), "r"(a[2]), "r"(a[3]), "r"(b0), "r"(b1));
}

// Split 2 floats into packed hi-bf16x2 (bit truncation) and lo-bf16x2 (residual)
__device__ __forceinline__ void split2(float a, float b, uint32_t& hi, uint32_t& lo) {
    uint32_t u0 = __float_as_uint(a), u1 = __float_as_uint(b);
    hi = (u0 >> 16) | (u1 & 0xffff0000u);
    float t0 = a - __uint_as_float(u0 & 0xffff0000u);
    float t1 = b - __uint_as_float(u1 & 0xffff0000u);
    __nv_bfloat162 b2 = __floats2bfloat162_rn(t0, t1);
    lo = *reinterpret_cast<uint32_t*>(&b2);
}

// ---------------------------------------------------------------------------
// zero degree array + detect edge dtype + zero the 64-wide padding rows
// ---------------------------------------------------------------------------
__global__ void zero_detect_kernel(const void* ei) {
    int i = blockIdx.x * blockDim.x + threadIdx.x;
    if (i < NN) g_deg[i] = 0;
    if (blockIdx.x == 0) {
        __shared__ int bad;
        if (threadIdx.x == 0) bad = 0;
        __syncthreads();
        const long long* p = (const long long*)ei;
        for (int j = threadIdx.x; j < 4096; j += blockDim.x) {
            long long v = p[j];
            if (v < 0 || v >= NN) bad = 1;
        }
        __syncthreads();
        if (threadIdx.x == 0) g_idx64 = bad ? 0 : 1;
    }
    if (blockIdx.x == 1 && threadIdx.x < 64) {
        g_h [(size_t)NN * 64 + threadIdx.x] = 0.f;
        g_h2[(size_t)NN * 64 + threadIdx.x] = 0.f;
    }
}

__global__ void bucket_fill_kernel(const void* ei) {
    int e = blockIdx.x * blockDim.x + threadIdx.x;
    if (e >= EE) return;
    int src, dst;
    if (g_idx64) {
        const long long* p = (const long long*)ei;
        src = (int)p[e];
        dst = (int)p[EE + e];
    } else {
        const int* p = (const int*)ei;
        src = p[e];
        dst = p[EE + e];
    }
    int pos = atomicAdd(&g_deg[dst], 1);
    if (pos < BCAP) g_bkt[(size_t)dst * BCAP + pos] = src;
}

__global__ void pad_kernel() {
    int i = blockIdx.x * blockDim.x + threadIdx.x;
    if (i >= NN) return;
    int d  = min(g_deg[i], BCAP);
    int d8 = (d + 7) & ~7;
    if (d8 < 8) d8 = 8;
    int* bp = &g_bkt[(size_t)i * BCAP];
    for (int j = d; j < d8; j++) bp[j] = NN;
    g_deg[i] = d8;
}

// ---------------------------------------------------------------------------
// HMMA GEMM: out[row0..row0+128, 0..DP) = in[.,64] @ W[64,wcols] (pad to DP).
// bf16 split: D = Ah@Bh + Al@Bh + Ah@Bl (fp32 accum, lo.lo dropped ~1.5e-5).
// A staged row-major [128][64]bf16 (stride 72), B staged as W^T [n][k] bf16
// (stride 72). Fragments loaded by direct LDS with the m16n8k16 lane map:
//   a0=A[g][2t] a1=A[g+8][2t] a2=A[g][2t+8] a3=A[g+8][2t+8]  (g=lane>>2,t=lane&3)
//   b0=Bt[g][2t] b1=Bt[g][2t+8]   (all contiguous bf16 pairs = one LDS.32)
// 8 warps x 16 rows; warp does NT n-tiles x 4 k-tiles x 3 splits HMMA.
// ZP (DP=48): zero the 48-wide pad row (before the LSM gather reads it).
// ---------------------------------------------------------------------------
template <int DP, bool ZP>   // DP = 64 or 48
__global__ void __launch_bounds__(256, 2)
gemm_mma_kernel(const float* __restrict__ in, const float* __restrict__ W,
                int wcols, float* __restrict__ out) {
    constexpr int NT = DP / 8;          // n-tiles (8 or 6)
    constexpr int BROWS = NT * 8;       // B rows staged (64 or 48)
    extern __shared__ char smem[];
    char* Ah = smem + AHI_OFF;
    char* Al = smem + ALO_OFF;
    char* Bh = smem + BHI_OFF;
    char* Bl = smem + BLO_OFF;

    const int tid = threadIdx.x;
    const int row0 = blockIdx.x * 128;

    if (ZP && blockIdx.x == 0 && tid < 64)
        out[(size_t)NN * 48 + tid] = 0.f;   // covers CH=12 sentinel reads

    // Stage B = W^T (hi/lo): Bt[n][k] = W[k][n], 8 k per chunk
    for (int chunk = tid; chunk < BROWS * 8; chunk += 256) {
        int n = chunk >> 3, k8 = chunk & 7;
        float f[8];
#pragma unroll
        for (int j = 0; j < 8; j++)
            f[j] = (n < wcols) ? W[(k8 * 8 + j) * wcols + n] : 0.f;
        uint32_t hi[4], lo[4];
#pragma unroll
        for (int p = 0; p < 4; p++) split2(f[2 * p], f[2 * p + 1], hi[p], lo[p]);
        int off = n * 144 + k8 * 16;
        *(uint4*)(Bh + off) = make_uint4(hi[0], hi[1], hi[2], hi[3]);
        *(uint4*)(Bl + off) = make_uint4(lo[0], lo[1], lo[2], lo[3]);
    }
    // Stage A (hi/lo): 128 rows x 64 cols, 8 cols per chunk
    const float4* in4 = (const float4*)in;
    for (int chunk = tid; chunk < 1024; chunk += 256) {
        int r = chunk >> 3, c8 = chunk & 7;
        int gr = row0 + r;
        float4 f0 = make_float4(0.f, 0.f, 0.f, 0.f), f1 = f0;
        if (gr < NN) {
            f0 = in4[(size_t)gr * 16 + c8 * 2];
            f1 = in4[(size_t)gr * 16 + c8 * 2 + 1];
        }
        uint32_t hi[4], lo[4];
        split2(f0.x, f0.y, hi[0], lo[0]);
        split2(f0.z, f0.w, hi[1], lo[1]);
        split2(f1.x, f1.y, hi[2], lo[2]);
        split2(f1.z, f1.w, hi[3], lo[3]);
        int off = r * 144 + c8 * 16;
        *(uint4*)(Ah + off) = make_uint4(hi[0], hi[1], hi[2], hi[3]);
        *(uint4*)(Al + off) = make_uint4(lo[0], lo[1], lo[2], lo[3]);
    }
    __syncthreads();

    const int w = tid >> 5, lane = tid & 31;
    const int g = lane >> 2, t = lane & 3;

    // Preload A fragments for all 4 k-tiles, hi and lo
    uint32_t ah[4][4], al[4][4];
    {
        int r0 = (w * 16 + g) * 144, r1 = (w * 16 + g + 8) * 144;
#pragma unroll
        for (int kt = 0; kt < 4; kt++) {
            int kb = kt * 32 + t * 4;
            ah[kt][0] = *(const uint32_t*)(Ah + r0 + kb);
            ah[kt][1] = *(const uint32_t*)(Ah + r1 + kb);
            ah[kt][2] = *(const uint32_t*)(Ah + r0 + kb + 16);
            ah[kt][3] = *(const uint32_t*)(Ah + r1 + kb + 16);
            al[kt][0] = *(const uint32_t*)(Al + r0 + kb);
            al[kt][1] = *(const uint32_t*)(Al + r1 + kb);
            al[kt][2] = *(const uint32_t*)(Al + r0 + kb + 16);
            al[kt][3] = *(const uint32_t*)(Al + r1 + kb + 16);
        }
    }

    float d[NT][4];
#pragma unroll
    for (int nt = 0; nt < NT; nt++)
#pragma unroll
        for (int j = 0; j < 4; j++) d[nt][j] = 0.f;

#pragma unroll
    for (int nt = 0; nt < NT; nt++) {
        int brow = (nt * 8 + g) * 144;
#pragma unroll
        for (int kt = 0; kt < 4; kt++) {
            int kb = kt * 32 + t * 4;
            uint32_t bh0 = *(const uint32_t*)(Bh + brow + kb);
            uint32_t bh1 = *(const uint32_t*)(Bh + brow + kb + 16);
            uint32_t bl0 = *(const uint32_t*)(Bl + brow + kb);
            uint32_t bl1 = *(const uint32_t*)(Bl + brow + kb + 16);
            mma16816(d[nt], ah[kt], bh0, bh1);   // hi*hi
            mma16816(d[nt], al[kt], bh0, bh1);   // lo*hi
            mma16816(d[nt], ah[kt], bl0, bl1);   // hi*lo
        }
    }

    // Epilogue: lane mapping c0=D[g][2t] c1=D[g][2t+1] c2/c3 = row g+8
    int r0 = row0 + w * 16 + g;
    int r1 = r0 + 8;
#pragma unroll
    for (int nt = 0; nt < NT; nt++) {
        int c = nt * 8 + t * 2;
        if (r0 < NN) *(float2*)&out[(size_t)r0 * DP + c] = make_float2(d[nt][0], d[nt][1]);
        if (r1 < NN) *(float2*)&out[(size_t)r1 * DP + c] = make_float2(d[nt][2], d[nt][3]);
    }
}

// ---------------------------------------------------------------------------
// Gather: out[n] = epi(bias + sum_{e in bkt[n]} h[src[e]]). 16 lanes/node.
// deg padded to >=8 multiple of 8: first 8-batch unconditional (do-while).
// ---------------------------------------------------------------------------
template <int CH, bool LSM>
__global__ void gather_kernel(const float* __restrict__ h,
                              const float* __restrict__ bias, int bcols,
                              float* __restrict__ outp) {
    int t = blockIdx.x * blockDim.x + threadIdx.x;
    int n = t >> 4;
    if (n >= NN) return;
    int ln = t & 15;

    const bool act = (ln < CH);
    float4 a = make_float4(0.f, 0.f, 0.f, 0.f);
    float4 b = a;
    if (act) {
        int c = ln * 4;
        a.x = bias[c];
        a.y = bias[c + 1];
        a.z = bias[c + 2];
        a.w = (c + 3 < bcols) ? bias[c + 3] : 0.f;
    }

    const int deg8 = g_deg[n];               // >= 8, multiple of 8
    const int* bp = &g_bkt[(size_t)n * BCAP];
    const float4* h4 = (const float4*)h;

    int e = 0;
    do {
        int4 i0 = *(const int4*)(bp + e);
        int4 i1 = *(const int4*)(bp + e + 4);
        if (act) {
            float4 v0 = h4[(size_t)i0.x * CH + ln];
            float4 v1 = h4[(size_t)i0.y * CH + ln];
            float4 v2 = h4[(size_t)i0.z * CH + ln];
            float4 v3 = h4[(size_t)i0.w * CH + ln];
            float4 v4 = h4[(size_t)i1.x * CH + ln];
            float4 v5 = h4[(size_t)i1.y * CH + ln];
            float4 v6 = h4[(size_t)i1.z * CH + ln];
            float4 v7 = h4[(size_t)i1.w * CH + ln];
            a.x += (v0.x + v1.x) + (v2.x + v3.x);
            a.y += (v0.y + v1.y) + (v2.y + v3.y);
            a.z += (v0.z + v1.z) + (v2.z + v3.z);
            a.w += (v0.w + v1.w) + (v2.w + v3.w);
            b.x += (v4.x + v5.x) + (v6.x + v7.x);
            b.y += (v4.y + v5.y) + (v6.y + v7.y);
            b.z += (v4.z + v5.z) + (v6.z + v7.z);
            b.w += (v4.w + v5.w) + (v6.w + v7.w);
        }
        e += 8;
    } while (e < deg8);
    a.x += b.x; a.y += b.y; a.z += b.z; a.w += b.w;

    if (!LSM) {
        a.x = fmaxf(a.x, 0.f); a.y = fmaxf(a.y, 0.f);
        a.z = fmaxf(a.z, 0.f); a.w = fmaxf(a.w, 0.f);
        if (act) ((float4*)outp)[(size_t)n * CH + ln] = a;
    } else {
        float e0 = a.x, e1 = a.y, e2 = a.z, e3 = a.w;
        bool v3ok = (ln * 4 + 3 < DOUT);
        if (!act)       { e0 = e1 = e2 = e3 = -INFINITY; }
        else if (!v3ok) { e3 = -INFINITY; }

        float m = fmaxf(fmaxf(e0, e1), fmaxf(e2, e3));
#pragma unroll
        for (int off = 8; off; off >>= 1)
            m = fmaxf(m, __shfl_xor_sync(0xFFFFFFFFu, m, off));

        float s = 0.f;
        if (act) {
            s = expf(e0 - m) + expf(e1 - m) + expf(e2 - m);
            if (v3ok) s += expf(e3 - m);
        }
#pragma unroll
        for (int off = 8; off; off >>= 1)
            s += __shfl_xor_sync(0xFFFFFFFFu, s, off);

        float lse = m + logf(s);
        if (act) {
            size_t o = (size_t)n * DOUT + ln * 4;
            outp[o]     = e0 - lse;
            outp[o + 1] = e1 - lse;
            outp[o + 2] = e2 - lse;
            if (v3ok) outp[o + 3] = e3 - lse;
        }
    }
}

// ---------------------------------------------------------------------------
extern "C" void kernel_launch(void* const* d_in, const int* in_sizes, int n_in,
                              void* d_out, int out_size) {
    const float* x  = (const float*)d_in[0];
    const void*  ei = d_in[1];
    const float* W1 = (const float*)d_in[2];
    const float* b1 = (const float*)d_in[3];
    const float* W2 = (const float*)d_in[4];
    const float* b2 = (const float*)d_in[5];
    const float* W3 = (const float*)d_in[6];
    const float* b3 = (const float*)d_in[7];
    float* out = (float*)d_out;

    float *h_ptr, *h2_ptr, *agg_ptr;
    cudaGetSymbolAddress((void**)&h_ptr,  g_h);
    cudaGetSymbolAddress((void**)&h2_ptr, g_h2);
    cudaGetSymbolAddress((void**)&agg_ptr, g_agg);

    static cudaStream_t s2 = nullptr;
    static cudaEvent_t evFork, evJoin;
    if (!s2) {
        cudaFuncSetAttribute(gemm_mma_kernel<64, false>,
                             cudaFuncAttributeMaxDynamicSharedMemorySize, SM_TOT);
        cudaFuncSetAttribute(gemm_mma_kernel<48, true>,
                             cudaFuncAttributeMaxDynamicSharedMemorySize, SM_TOT);
        cudaStreamCreateWithFlags(&s2, cudaStreamNonBlocking);
        cudaEventCreateWithFlags(&evFork, cudaEventDisableTiming);
        cudaEventCreateWithFlags(&evJoin, cudaEventDisableTiming);
    }

    const int EDGE_BLKS = (EE + 255) / 256;                    // 3125
    const int NODE_BLKS = (NN + 255) / 256;                    // 391
    const int GATH_BLKS = ((long long)NN * 16 + 255) / 256;    // 6250

    // --- Fork: bucket build + padding on s2, concurrent with layer-1 GEMM ---
    cudaEventRecord(evFork, 0);
    cudaStreamWaitEvent(s2, evFork, 0);
    zero_detect_kernel<<<NODE_BLKS, 256, 0, s2>>>(ei);           // launch 1
    bucket_fill_kernel<<<EDGE_BLKS, 256, 0, s2>>>(ei);           // launch 2
    pad_kernel<<<NODE_BLKS, 256, 0, s2>>>();                     // launch 3
    cudaEventRecord(evJoin, s2);

    // Layer-1 GEMM (HMMA) on main stream: g_h = x @ W1
    gemm_mma_kernel<64, false><<<GTILES, 256, SM_TOT>>>(x, W1, 64, h_ptr); // 4
    cudaStreamWaitEvent(0, evJoin, 0);

    // Layer 1 aggregate
    gather_kernel<16, false><<<GATH_BLKS, 256>>>(h_ptr, b1, 64, agg_ptr);  // 5

    // Layer 2 (launch 6 — ncu capture target: gemm2)
    gemm_mma_kernel<64, false><<<GTILES, 256, SM_TOT>>>(agg_ptr, W2, 64, h2_ptr);
    gather_kernel<16, false><<<GATH_BLKS, 256>>>(h2_ptr, b2, 64, agg_ptr);

    // Layer 3 (48-wide, zeroes its own pad row) + fused log_softmax
    gemm_mma_kernel<48, true><<<GTILES, 256, SM_TOT>>>(agg_ptr, W3, 47, h_ptr);
    gather_kernel<12, true><<<GATH_BLKS, 256>>>(h_ptr, b3, 47, out);
}